// round 8
// baseline (speedup 1.0000x reference)
#include <cuda_runtime.h>
#include <cstdint>

// out[b,co,h,w] = sum_{kh,kw,cin} xpad[b,cin,h+kh-1,w+kw-1] * (exp(k[kh,kw,cin,co]+5) - delta_w)
//              + sum_r exp(k_r+5) - delta_x * sum_r k_r + bias[co]
// alpha=1 so exp(lse) = sum exp(z); exp(log(x+1)) = x+1; zero-padded lnx
// positions give exp(0)=1 == the (x+1) form at x=0. The -xp*delta_w term is
// an all-ones conv of x folded into W'' = e - delta_w.
//
// R8: single-wave occupancy (4 blocks/SM via 64-reg cap + smem aliasing) and
// pre-duplicated x in smem ({v,v} pairs, LDS.64) so the f32x2 inner loop has
// zero MOV duplication on the alu pipe.

#define B_     8
#define CIN_   32
#define H_     28
#define W_     28
#define COUT_  64
#define R_     288

constexpr int TR   = 4;    // output rows per block (7 tiles cover 28)
constexpr int CG   = 8;    // couts per block
constexpr int NTHR = 256;  // 8 warps, K-split: warp w -> cin [4w, 4w+4)
constexpr int XR   = 6;    // TR + 2 input rows
constexpr int XROW = 30;   // cols -1..28 (lane+kw <= 29)
constexpr int XN   = CIN_ * XR * XROW;     // 5760 duplicated-pair elements (8B each)

// dynamic smem layout (bytes). sP / redE / redK alias the sX region:
//   sX  : Phase C..D   [0, 46080)
//   sP  : Phase E      [0, 14336)         (after post-D sync)
//   redE/redK : Phase A..B [16384, 18432) (before sX is written)
constexpr int OFF_X  = 0;
constexpr int OFF_P  = 0;
constexpr int OFF_RE = 16384;
constexpr int OFF_RK = 17408;
constexpr int OFF_W  = XN * 8;             // 46080, sW: 288*8*4 = 9216
constexpr int OFF_C  = OFF_W + R_ * CG * 4;// 55296, sC: 8*4
constexpr int SMEM_TOTAL = OFF_C + 32;     // 55328 -> 4 blocks/SM

__global__ void __launch_bounds__(NTHR, 4) fused_conv_kernel(
    const float* __restrict__ x,
    const float* __restrict__ k,
    const float* __restrict__ bias,
    const float* __restrict__ dxp,
    const float* __restrict__ dwp,
    float* __restrict__ out)
{
    extern __shared__ __align__(16) char sm[];
    float* sW   = reinterpret_cast<float*>(sm + OFF_W);
    float* sC   = reinterpret_cast<float*>(sm + OFF_C);
    float* redE = reinterpret_cast<float*>(sm + OFF_RE);
    float* redK = reinterpret_cast<float*>(sm + OFF_RK);

    const int tid    = threadIdx.x;
    const int rt     = blockIdx.x;          // 0..6 row tile
    const int b      = blockIdx.y;          // 0..7 batch
    const int cg     = blockIdx.z;          // 0..7 cout group
    const int row0   = rt * TR;
    const int cobase = cg * CG;

    const float dw = dwp[0];
    const float dx = dxp[0];

    // ---- Phase A: weight transform (exp) + partial sums for C[co] ----
    {
        const int co  = tid & 7;            // local cout
        const int seg = tid >> 3;           // 0..31
        float se = 0.f, sk = 0.f;
        #pragma unroll
        for (int rr = seg; rr < R_; rr += 32) {
            float kv = k[rr * COUT_ + cobase + co];
            float e  = expf(kv + 5.0f);
            sW[rr * CG + co] = e - dw;
            se += e;
            sk += kv;
        }
        redE[co * 32 + seg] = se;
        redK[co * 32 + seg] = sk;
    }
    __syncthreads();

    // ---- Phase B: finish C[co] reduction (before sX overwrites red region) ----
    if (tid < CG) {
        float S = 0.f, K = 0.f;
        #pragma unroll
        for (int i = 0; i < 32; i++) { S += redE[tid * 32 + i]; K += redK[tid * 32 + i]; }
        sC[tid] = S - dx * K + bias[cobase + tid];
    }
    __syncthreads();

    // ---- Phase C: x tile as duplicated pairs {v,v}, rows row0-1..row0+4, cols -1..28 ----
    {
        const float* xb = x + (size_t)b * (CIN_ * H_ * W_);
        for (int idx = tid; idx < XN; idx += NTHR) {
            int c   = idx / (XR * XROW);
            int rem = idx - c * (XR * XROW);
            int rr  = rem / XROW;
            int cc  = rem - rr * XROW;
            int ir  = row0 - 1 + rr;
            int ic  = cc - 1;
            float v = 0.f;
            if ((unsigned)ir < (unsigned)H_ && (unsigned)ic < (unsigned)W_)
                v = xb[(c * H_ + ir) * W_ + ic];
            *reinterpret_cast<float2*>(sm + OFF_X + (size_t)idx * 8) = make_float2(v, v);
        }
    }
    __syncthreads();

    // ---- Phase D: conv. warp w: cin [4w,4w+4); thread: 4 rows x 8 couts ----
    const int wid  = tid >> 5;
    const int lane = tid & 31;
    const int c0   = wid * 4;

    unsigned long long acc[16];             // acc[r*4 + coutpair]
    #pragma unroll
    for (int i = 0; i < 16; i++) acc[i] = 0ull;

    if (lane < 28) {
        #pragma unroll
        for (int kh = 0; kh < 3; kh++) {
            #pragma unroll
            for (int kw = 0; kw < 3; kw++) {
                const char* xpb = sm + OFF_X + (size_t)((c0 * XR + kh) * XROW + lane + kw) * 8;
                const float* wp = &sW[((kh * 3 + kw) * CIN_ + c0) * CG];
                #pragma unroll
                for (int c = 0; c < 4; c++) {
                    unsigned long long xv[TR];
                    #pragma unroll
                    for (int r = 0; r < TR; r++)
                        xv[r] = *reinterpret_cast<const unsigned long long*>(
                                    xpb + (size_t)(c * (XR * XROW) + r * XROW) * 8);
                    ulonglong2 wA = *reinterpret_cast<const ulonglong2*>(wp + c * CG);
                    ulonglong2 wB = *reinterpret_cast<const ulonglong2*>(wp + c * CG + 4);
                    #pragma unroll
                    for (int r = 0; r < TR; r++) {
                        asm("fma.rn.f32x2 %0, %1, %2, %3;" : "=l"(acc[r*4+0]) : "l"(xv[r]), "l"(wA.x), "l"(acc[r*4+0]));
                        asm("fma.rn.f32x2 %0, %1, %2, %3;" : "=l"(acc[r*4+1]) : "l"(xv[r]), "l"(wA.y), "l"(acc[r*4+1]));
                        asm("fma.rn.f32x2 %0, %1, %2, %3;" : "=l"(acc[r*4+2]) : "l"(xv[r]), "l"(wB.x), "l"(acc[r*4+2]));
                        asm("fma.rn.f32x2 %0, %1, %2, %3;" : "=l"(acc[r*4+3]) : "l"(xv[r]), "l"(wB.y), "l"(acc[r*4+3]));
                    }
                }
            }
        }
    }
    __syncthreads();   // sX no longer needed; sP may alias it from here on

    // ---- Phase E: 8-way K reduction (f32x2 tree in aliased smem) ----
    unsigned long long* sP = reinterpret_cast<unsigned long long*>(sm + OFF_P);

    if (wid >= 4 && lane < 28) {
        unsigned long long* p = sP + ((wid - 4) * 16) * 28 + lane;
        #pragma unroll
        for (int j = 0; j < 16; j++) p[j * 28] = acc[j];
    }
    __syncthreads();
    if (wid < 4 && lane < 28) {
        const unsigned long long* p = sP + (wid * 16) * 28 + lane;
        #pragma unroll
        for (int j = 0; j < 16; j++) {
            unsigned long long v = p[j * 28];
            asm("add.rn.f32x2 %0, %1, %2;" : "=l"(acc[j]) : "l"(acc[j]), "l"(v));
        }
    }
    __syncthreads();
    if (wid >= 1 && wid < 4 && lane < 28) {
        unsigned long long* p = sP + (wid * 16) * 28 + lane;
        #pragma unroll
        for (int j = 0; j < 16; j++) p[j * 28] = acc[j];
    }
    __syncthreads();

    if (wid == 0 && lane < 28) {
        #pragma unroll
        for (int w = 1; w < 4; w++) {
            const unsigned long long* p = sP + (w * 16) * 28 + lane;
            #pragma unroll
            for (int j = 0; j < 16; j++) {
                unsigned long long v = p[j * 28];
                asm("add.rn.f32x2 %0, %1, %2;" : "=l"(acc[j]) : "l"(acc[j]), "l"(v));
            }
        }

        float* o = out + (((size_t)b * COUT_ + cobase) * H_ + row0) * W_ + lane;
        #pragma unroll
        for (int r = 0; r < TR; r++) {
            #pragma unroll
            for (int j = 0; j < 4; j++) {
                unsigned long long a = acc[r*4+j];
                float lo = __uint_as_float((uint32_t)a)         + sC[2*j];
                float hi = __uint_as_float((uint32_t)(a >> 32)) + sC[2*j+1];
                o[(size_t)(2*j  ) * (H_*W_) + r * W_] = lo;
                o[(size_t)(2*j+1) * (H_*W_) + r * W_] = hi;
            }
        }
    }
}

extern "C" void kernel_launch(void* const* d_in, const int* in_sizes, int n_in,
                              void* d_out, int out_size)
{
    (void)in_sizes; (void)n_in; (void)out_size;
    const float* x    = (const float*)d_in[0];
    const float* k    = (const float*)d_in[1];
    const float* bias = (const float*)d_in[2];
    const float* dx   = (const float*)d_in[3];
    const float* dw   = (const float*)d_in[4];
    float* out        = (float*)d_out;

    cudaFuncSetAttribute(fused_conv_kernel,
                         cudaFuncAttributeMaxDynamicSharedMemorySize, SMEM_TOTAL);

    dim3 grid(7, B_, COUT_ / CG);   // 448 blocks x 8 warps; occ 4/SM -> single wave
    fused_conv_kernel<<<grid, NTHR, SMEM_TOTAL>>>(x, k, bias, dx, dw, out);
}

// round 9
// speedup vs baseline: 2.2662x; 2.2662x over previous
#include <cuda_runtime.h>
#include <cstdint>

// out[b,co,h,w] = sum_{kh,kw,cin} xpad[b,cin,h+kh-1,w+kw-1] * (exp(k[kh,kw,cin,co]+5) - delta_w)
//              + sum_r exp(k_r+5) - delta_x * sum_r k_r + bias[co]
// alpha=1 so exp(lse) = sum exp(z); exp(log(x+1)) = x+1; zero-padded lnx
// positions give exp(0)=1 == the (x+1) form at x=0. The -xp*delta_w term is
// an all-ones conv of x folded into W'' = e - delta_w.
//
// R9: 128-thr blocks, TR=2, 4-way K-split (acc[8] -> ~50 regs, cap 73 is
// spill-safe), grid 896 fully co-resident at 7 blocks/SM -> no serialized
// tail. sP reduction buffers alias sX; weight phase runs parallel to x load.

#define B_     8
#define CIN_   32
#define H_     28
#define W_     28
#define COUT_  64
#define R_     288

constexpr int TR   = 2;    // output rows per block (14 tiles)
constexpr int CG   = 8;    // couts per block
constexpr int NTHR = 128;  // 4 warps; warp w -> cin [8w, 8w+8)
constexpr int XR   = 4;    // TR + 2 input rows
constexpr int XROW = 32;
constexpr int XSZ  = CIN_ * XR * XROW;     // 4096 floats = 16 KB

// smem layout (bytes); sP aliases sX (disjoint in time, sync-protected)
constexpr int OFF_X  = 0;                  // 16384
constexpr int OFF_P  = 0;                  // 3584 used (2 bufs x 8x28 u64)
constexpr int OFF_W  = 16384;              // 9216
constexpr int OFF_RE = 25600;              // 512
constexpr int OFF_RK = 26112;              // 512
constexpr int OFF_C  = 26624;              // 32
constexpr int SMEMB  = 26656;

__global__ void __launch_bounds__(NTHR, 7) fused_conv_kernel(
    const float* __restrict__ x,
    const float* __restrict__ k,
    const float* __restrict__ bias,
    const float* __restrict__ dxp,
    const float* __restrict__ dwp,
    float* __restrict__ out)
{
    __shared__ __align__(16) char sm[SMEMB];
    float* sX   = reinterpret_cast<float*>(sm + OFF_X);
    float* sW   = reinterpret_cast<float*>(sm + OFF_W);
    float* redE = reinterpret_cast<float*>(sm + OFF_RE);
    float* redK = reinterpret_cast<float*>(sm + OFF_RK);
    float* sC   = reinterpret_cast<float*>(sm + OFF_C);

    const int tid    = threadIdx.x;
    const int rt     = blockIdx.x;          // 0..13 row tile
    const int b      = blockIdx.y;          // 0..7 batch
    const int cg     = blockIdx.z;          // 0..7 cout group
    const int row0   = rt * TR;
    const int cobase = cg * CG;

    const float dw = dwp[0];
    const float dx = dxp[0];

    // ---- Phase A: weight transform (exp) + partial sums for C[co] ----
    {
        const int co  = tid & 7;
        const int seg = tid >> 3;           // 0..15
        float se = 0.f, sk = 0.f;
        #pragma unroll
        for (int rr = seg; rr < R_; rr += 16) {
            float kv = k[rr * COUT_ + cobase + co];
            float e  = expf(kv + 5.0f);
            sW[rr * CG + co] = e - dw;
            se += e;
            sk += kv;
        }
        redE[co * 16 + seg] = se;
        redK[co * 16 + seg] = sk;
    }

    // ---- Phase C: x tile, rows row0-1..row0+2, cols -1..30, zero pad ----
    {
        const float* xb = x + (size_t)b * (CIN_ * H_ * W_);
        #pragma unroll
        for (int i = 0; i < XSZ / NTHR; i++) {
            int idx = i * NTHR + tid;
            int c   = idx >> 7;             // /(XR*XROW)=128
            int rem = idx & 127;
            int rr  = rem >> 5;             // 0..3
            int cc  = rem & 31;
            int ir  = row0 - 1 + rr;
            int ic  = cc - 1;
            float v = 0.f;
            if ((unsigned)ir < (unsigned)H_ && (unsigned)ic < (unsigned)W_)
                v = xb[(c * H_ + ir) * W_ + ic];
            sX[idx] = v;
        }
    }
    __syncthreads();

    // ---- Phase B: finish C[co] reduction ----
    if (tid < CG) {
        float S = 0.f, K = 0.f;
        #pragma unroll
        for (int i = 0; i < 16; i++) { S += redE[tid * 16 + i]; K += redK[tid * 16 + i]; }
        sC[tid] = S - dx * K + bias[cobase + tid];
    }

    // ---- Phase D: conv. warp w: cin [8w,8w+8); thread: 2 rows x 8 couts ----
    const int wid  = tid >> 5;
    const int lane = tid & 31;
    const int c0   = wid * 8;

    unsigned long long acc[8];              // acc[r*4 + coutpair]
    #pragma unroll
    for (int i = 0; i < 8; i++) acc[i] = 0ull;

    if (lane < 28) {
        #pragma unroll
        for (int kh = 0; kh < 3; kh++) {
            #pragma unroll
            for (int kw = 0; kw < 3; kw++) {
                const float* xp = &sX[(c0 * XR + kh) * XROW + lane + kw];
                const float* wp = &sW[((kh * 3 + kw) * CIN_ + c0) * CG];
                #pragma unroll
                for (int c = 0; c < 8; c++) {
                    unsigned long long xv0, xv1;
                    {
                        uint32_t u0 = __float_as_uint(xp[c * (XR * XROW)]);
                        uint32_t u1 = __float_as_uint(xp[c * (XR * XROW) + XROW]);
                        asm("mov.b64 %0, {%1, %1};" : "=l"(xv0) : "r"(u0));
                        asm("mov.b64 %0, {%1, %1};" : "=l"(xv1) : "r"(u1));
                    }
                    ulonglong2 wA = *reinterpret_cast<const ulonglong2*>(wp + c * CG);
                    ulonglong2 wB = *reinterpret_cast<const ulonglong2*>(wp + c * CG + 4);
                    asm("fma.rn.f32x2 %0, %1, %2, %3;" : "=l"(acc[0]) : "l"(xv0), "l"(wA.x), "l"(acc[0]));
                    asm("fma.rn.f32x2 %0, %1, %2, %3;" : "=l"(acc[1]) : "l"(xv0), "l"(wA.y), "l"(acc[1]));
                    asm("fma.rn.f32x2 %0, %1, %2, %3;" : "=l"(acc[2]) : "l"(xv0), "l"(wB.x), "l"(acc[2]));
                    asm("fma.rn.f32x2 %0, %1, %2, %3;" : "=l"(acc[3]) : "l"(xv0), "l"(wB.y), "l"(acc[3]));
                    asm("fma.rn.f32x2 %0, %1, %2, %3;" : "=l"(acc[4]) : "l"(xv1), "l"(wA.x), "l"(acc[4]));
                    asm("fma.rn.f32x2 %0, %1, %2, %3;" : "=l"(acc[5]) : "l"(xv1), "l"(wA.y), "l"(acc[5]));
                    asm("fma.rn.f32x2 %0, %1, %2, %3;" : "=l"(acc[6]) : "l"(xv1), "l"(wB.x), "l"(acc[6]));
                    asm("fma.rn.f32x2 %0, %1, %2, %3;" : "=l"(acc[7]) : "l"(xv1), "l"(wB.y), "l"(acc[7]));
                }
            }
        }
    }
    __syncthreads();   // sX dead; sP may alias

    // ---- Phase E: 4-way K reduction (f32x2 tree in aliased smem) ----
    unsigned long long* sP = reinterpret_cast<unsigned long long*>(sm + OFF_P);

    if (wid >= 2 && lane < 28) {
        unsigned long long* p = sP + ((wid - 2) * 8) * 28 + lane;
        #pragma unroll
        for (int j = 0; j < 8; j++) p[j * 28] = acc[j];
    }
    __syncthreads();
    if (wid < 2 && lane < 28) {
        const unsigned long long* p = sP + (wid * 8) * 28 + lane;
        #pragma unroll
        for (int j = 0; j < 8; j++) {
            unsigned long long v = p[j * 28];
            asm("add.rn.f32x2 %0, %1, %2;" : "=l"(acc[j]) : "l"(acc[j]), "l"(v));
        }
    }
    __syncthreads();
    if (wid == 1 && lane < 28) {
        unsigned long long* p = sP + lane;
        #pragma unroll
        for (int j = 0; j < 8; j++) p[j * 28] = acc[j];
    }
    __syncthreads();

    if (wid == 0 && lane < 28) {
        const unsigned long long* p = sP + lane;
        #pragma unroll
        for (int j = 0; j < 8; j++) {
            unsigned long long v = p[j * 28];
            asm("add.rn.f32x2 %0, %1, %2;" : "=l"(acc[j]) : "l"(acc[j]), "l"(v));
        }

        float* o = out + (((size_t)b * COUT_ + cobase) * H_ + row0) * W_ + lane;
        #pragma unroll
        for (int r = 0; r < TR; r++) {
            #pragma unroll
            for (int j = 0; j < 4; j++) {
                unsigned long long a = acc[r*4+j];
                float lo = __uint_as_float((uint32_t)a)         + sC[2*j];
                float hi = __uint_as_float((uint32_t)(a >> 32)) + sC[2*j+1];
                o[(size_t)(2*j  ) * (H_*W_) + r * W_] = lo;
                o[(size_t)(2*j+1) * (H_*W_) + r * W_] = hi;
            }
        }
    }
}

extern "C" void kernel_launch(void* const* d_in, const int* in_sizes, int n_in,
                              void* d_out, int out_size)
{
    (void)in_sizes; (void)n_in; (void)out_size;
    const float* x    = (const float*)d_in[0];
    const float* k    = (const float*)d_in[1];
    const float* bias = (const float*)d_in[2];
    const float* dx   = (const float*)d_in[3];
    const float* dw   = (const float*)d_in[4];
    float* out        = (float*)d_out;

    dim3 grid(14, B_, COUT_ / CG);   // 896 blocks x 4 warps; 7/SM -> all co-resident
    fused_conv_kernel<<<grid, NTHR>>>(x, k, bias, dx, dw, out);
}

// round 11
// speedup vs baseline: 3.0525x; 1.3469x over previous
#include <cuda_runtime.h>
#include <cuda_bf16.h>
#include <cstdint>

// Algebraic collapse (alpha=1): exp(lse) = sum_r exp(ln(x_r+1)+k_r+5) = sum_r (x_r+1)e^{k_r+5}
// -> out[m,co] = sum_r A[m,r]*W''[r,co] + C[co]
//    A = im2col(x) (zero pad), W'' = e^{k+5} - delta_w, C = sum e - dx*sum k + bias.
// GEMM M=6272(=98x64), N=64, K=288(=18 k16 steps) via mma.sync.m16n8k16 bf16
// (baseline PTX -- the harness targets compute_103, so no tcgen05/'a' features).
// fp32 accumulation; bf16 rounding of x/W'' is ~1e-4 relative vs the large C term.

#define B_   8
#define H_   28
#define W_   28

// scratch (alloc-free rule: __device__ globals)
__device__ uint4 g_xt4[8 * 30 * 30 * 4];   // bf16 [8][30][30][32], padded borders = 0
__device__ uint4 g_w4[64 * 40];            // bf16 [64][320] = W''^T, cols 288..319 = 0
__device__ float g_C[64];

__device__ __forceinline__ uint32_t smem_u32(const void* p) {
    uint32_t a;
    asm("{ .reg .u64 t; cvta.to.shared.u64 t, %1; cvt.u32.u64 %0, t; }" : "=r"(a) : "l"(p));
    return a;
}
__device__ __forceinline__ void ldmx4(uint32_t* r, uint32_t addr) {
    asm volatile("ldmatrix.sync.aligned.m8n8.x4.shared.b16 {%0,%1,%2,%3}, [%4];"
                 : "=r"(r[0]), "=r"(r[1]), "=r"(r[2]), "=r"(r[3]) : "r"(addr));
}
__device__ __forceinline__ void mma16816(float* d, const uint32_t* a,
                                         uint32_t b0, uint32_t b1) {
    asm volatile(
        "mma.sync.aligned.m16n8k16.row.col.f32.bf16.bf16.f32 "
        "{%0,%1,%2,%3}, {%4,%5,%6,%7}, {%8,%9}, {%0,%1,%2,%3};"
        : "+f"(d[0]), "+f"(d[1]), "+f"(d[2]), "+f"(d[3])
        : "r"(a[0]), "r"(a[1]), "r"(a[2]), "r"(a[3]), "r"(b0), "r"(b1));
}

// ---------------- Kernel 1: prep (weights + x transpose/pad) ----------------
__global__ void __launch_bounds__(320) prep_kernel(
    const float* __restrict__ x, const float* __restrict__ k,
    const float* __restrict__ bias,
    const float* __restrict__ dxp, const float* __restrict__ dwp)
{
    __shared__ float pe[320], pk[320];
    const int tid = threadIdx.x;

    if (blockIdx.x < 64) {
        // ---- weights: W''^T[co][r] = exp(k[r,co]+5) - dw ; C[co] ----
        const int co = blockIdx.x;
        __nv_bfloat16* w2 = reinterpret_cast<__nv_bfloat16*>(g_w4);
        float e = 0.f, kv = 0.f;
        if (tid < 288) {
            kv = k[tid * 64 + co];
            e  = expf(kv + 5.0f);
            w2[co * 320 + tid] = __float2bfloat16(e - dwp[0]);
        } else {
            w2[co * 320 + tid] = __float2bfloat16(0.f);
        }
        pe[tid] = e; pk[tid] = kv;
        __syncthreads();
        for (int s = 160; s >= 5; s >>= 1) {
            if (tid < s) { pe[tid] += pe[tid + s]; pk[tid] += pk[tid + s]; }
            __syncthreads();
        }
        if (tid == 0) {
            float SE = pe[0] + pe[1] + pe[2] + pe[3] + pe[4];
            float SK = pk[0] + pk[1] + pk[2] + pk[3] + pk[4];
            g_C[co] = SE - dxp[0] * SK + bias[co];
        }
    } else {
        // ---- x -> bf16 [b][hp][wp][ci], zero borders (pad=1) ----
        int p = (blockIdx.x - 64) * 320 + tid;
        if (p < 7200) {
            int b   = p / 900, rem = p - b * 900;
            int hp  = rem / 30, wp = rem - hp * 30;
            if (hp == 0 || hp == 29 || wp == 0 || wp == 29) {
                uint4 z = make_uint4(0, 0, 0, 0);
                g_xt4[p * 4 + 0] = z; g_xt4[p * 4 + 1] = z;
                g_xt4[p * 4 + 2] = z; g_xt4[p * 4 + 3] = z;
            } else {
                const float* xs = x + (size_t)b * 32 * 784 + (hp - 1) * 28 + (wp - 1);
                __nv_bfloat162 buf[16];
                #pragma unroll
                for (int j = 0; j < 16; j++)
                    buf[j] = __floats2bfloat162_rn(xs[(2 * j) * 784], xs[(2 * j + 1) * 784]);
                const uint4* u = reinterpret_cast<const uint4*>(buf);
                g_xt4[p * 4 + 0] = u[0]; g_xt4[p * 4 + 1] = u[1];
                g_xt4[p * 4 + 2] = u[2]; g_xt4[p * 4 + 3] = u[3];
            }
        }
    }
}

// ---------------- Kernel 2: implicit-GEMM conv via HMMA ----------------
// smem: A 64 rows x 592B (stride 37 uint4, conflict-free ldmatrix), B same, C.
constexpr int STRB  = 592;                 // 37 * 16
constexpr int OFF_A = 0;                   // 64*592 = 37888
constexpr int OFF_B = 37888;               // 64*592 = 37888
constexpr int OFF_C = 75776;               // 64 floats
constexpr int SMEMB = OFF_C + 256;

__global__ void __launch_bounds__(256) conv_mma_kernel(float* __restrict__ out)
{
    extern __shared__ __align__(16) char sm[];
    const uint32_t smb = smem_u32(sm);
    uint4* sA4 = reinterpret_cast<uint4*>(sm + OFF_A);
    uint4* sB4 = reinterpret_cast<uint4*>(sm + OFF_B);
    float* sC  = reinterpret_cast<float*>(sm + OFF_C);

    const int tid  = threadIdx.x;
    const int wid  = tid >> 5;
    const int lane = tid & 31;
    const int t    = blockIdx.x;            // M-tile (98 tiles of 64 rows)

    if (tid < 64) sC[tid] = g_C[tid];

    // ---- stage A (im2col rows) and B (W''^T) into smem ----
    #pragma unroll
    for (int i = 0; i < 9; i++) {           // 64*36 / 256 = 9
        int q   = i * 256 + tid;
        int row = q / 36;
        int c36 = q - row * 36;
        // A
        {
            int seg = c36 >> 2, c4 = c36 & 3;
            int kh  = seg / 3,  kw = seg - kh * 3;
            int m   = t * 64 + row;
            int b   = m / 784, rem = m - b * 784;
            int h   = rem / 28, w = rem - h * 28;
            sA4[row * 37 + c36] = g_xt4[((b * 30 + h + kh) * 30 + (w + kw)) * 4 + c4];
        }
        // B
        sB4[row * 37 + c36] = g_w4[row * 40 + c36];
    }
    __syncthreads();

    // ---- warp tiling: 8 warps = 4(M) x 2(N); warp tile 16M x 32N ----
    const int wm = (wid & 3) * 16;
    const int wn = (wid >> 2) * 32;

    uint32_t aAddr  = smb + OFF_A + (uint32_t)(wm + (lane & 15)) * STRB + (lane >> 4) * 16;
    uint32_t b0Addr = smb + OFF_B + (uint32_t)(wn + (lane & 15)) * STRB + (lane >> 4) * 16;
    uint32_t b1Addr = b0Addr + 16u * STRB;

    float acc[16];
    #pragma unroll
    for (int i = 0; i < 16; i++) acc[i] = 0.f;

    #pragma unroll
    for (int ks = 0; ks < 18; ks++) {
        uint32_t a[4], b0[4], b1[4];
        ldmx4(a,  aAddr  + ks * 32);
        ldmx4(b0, b0Addr + ks * 32);
        ldmx4(b1, b1Addr + ks * 32);
        // b0: {n0k0, n1k0, n0k1, n1k1} for n-tiles 0,1 ; b1 for n-tiles 2,3
        mma16816(acc + 0,  a, b0[0], b0[2]);
        mma16816(acc + 4,  a, b0[1], b0[3]);
        mma16816(acc + 8,  a, b1[0], b1[2]);
        mma16816(acc + 12, a, b1[1], b1[3]);
    }

    // ---- epilogue: D frag -> out[b][co][h][w] + C[co] ----
    {
        const int row  = lane >> 2;
        const int colp = (lane & 3) * 2;
        int m0 = t * 64 + wm + row;
        int m1 = m0 + 8;
        int b0i = m0 / 784, r0 = m0 - b0i * 784;
        int b1i = m1 / 784, r1 = m1 - b1i * 784;
        float* o0 = out + (size_t)b0i * 64 * 784 + r0;
        float* o1 = out + (size_t)b1i * 64 * 784 + r1;
        #pragma unroll
        for (int j = 0; j < 4; j++) {
            int co = wn + j * 8 + colp;
            float c0 = sC[co], c1 = sC[co + 1];
            o0[(size_t)(co    ) * 784] = acc[j * 4 + 0] + c0;
            o0[(size_t)(co + 1) * 784] = acc[j * 4 + 1] + c1;
            o1[(size_t)(co    ) * 784] = acc[j * 4 + 2] + c0;
            o1[(size_t)(co + 1) * 784] = acc[j * 4 + 3] + c1;
        }
    }
}

// ---------------- launch ----------------
extern "C" void kernel_launch(void* const* d_in, const int* in_sizes, int n_in,
                              void* d_out, int out_size)
{
    (void)in_sizes; (void)n_in; (void)out_size;
    const float* x    = (const float*)d_in[0];
    const float* k    = (const float*)d_in[1];
    const float* bias = (const float*)d_in[2];
    const float* dx   = (const float*)d_in[3];
    const float* dw   = (const float*)d_in[4];
    float* out        = (float*)d_out;

    cudaFuncSetAttribute(conv_mma_kernel,
                         cudaFuncAttributeMaxDynamicSharedMemorySize, SMEMB);

    prep_kernel<<<87, 320>>>(x, k, bias, dx, dw);   // 64 weight + 23 x-transpose blocks
    conv_mma_kernel<<<98, 256, SMEMB>>>(out);       // one 64-row M-tile per CTA, single wave
}

// round 12
// speedup vs baseline: 3.1254x; 1.0239x over previous
#include <cuda_runtime.h>
#include <cuda_bf16.h>
#include <cstdint>

// Algebraic collapse (alpha=1): exp(lse) = sum_r exp(ln(x_r+1)+k_r+5) = sum_r (x_r+1)e^{k_r+5}
// -> out[m,co] = sum_r A[m,r]*W''[r,co] + C[co]
//    A = im2col(x) (zero pad), W'' = e^{k+5} - delta_w, C = sum e - dx*sum k + bias.
// GEMM M=6272(=98x64), N=64, K=288(=18 k16 steps) via mma.sync.m16n8k16 bf16.
// R12: 512-thr conv blocks (16 warps, warp-tile 16x16), 2 K-chains (9-deep),
// __expf in prep. Latency-bound fix: 2x warps/SMSP, halved per-warp path.

#define B_   8
#define H_   28
#define W_   28

// scratch (alloc-free rule: __device__ globals)
__device__ uint4 g_xt4[8 * 30 * 30 * 4];   // bf16 [8][30][30][32], padded borders = 0
__device__ uint4 g_w4[64 * 40];            // bf16 [64][320] = W''^T, cols 288..319 = 0
__device__ float g_C[64];

__device__ __forceinline__ uint32_t smem_u32(const void* p) {
    uint32_t a;
    asm("{ .reg .u64 t; cvta.to.shared.u64 t, %1; cvt.u32.u64 %0, t; }" : "=r"(a) : "l"(p));
    return a;
}
__device__ __forceinline__ void ldmx4(uint32_t* r, uint32_t addr) {
    asm volatile("ldmatrix.sync.aligned.m8n8.x4.shared.b16 {%0,%1,%2,%3}, [%4];"
                 : "=r"(r[0]), "=r"(r[1]), "=r"(r[2]), "=r"(r[3]) : "r"(addr));
}
__device__ __forceinline__ void mma16816(float* d, const uint32_t* a,
                                         uint32_t b0, uint32_t b1) {
    asm volatile(
        "mma.sync.aligned.m16n8k16.row.col.f32.bf16.bf16.f32 "
        "{%0,%1,%2,%3}, {%4,%5,%6,%7}, {%8,%9}, {%0,%1,%2,%3};"
        : "+f"(d[0]), "+f"(d[1]), "+f"(d[2]), "+f"(d[3])
        : "r"(a[0]), "r"(a[1]), "r"(a[2]), "r"(a[3]), "r"(b0), "r"(b1));
}

// ---------------- Kernel 1: prep (weights + x transpose/pad) ----------------
__global__ void __launch_bounds__(320) prep_kernel(
    const float* __restrict__ x, const float* __restrict__ k,
    const float* __restrict__ bias,
    const float* __restrict__ dxp, const float* __restrict__ dwp)
{
    __shared__ float pe[320], pk[320];
    const int tid = threadIdx.x;

    if (blockIdx.x < 64) {
        // ---- weights: W''^T[co][r] = exp(k[r,co]+5) - dw ; C[co] ----
        const int co = blockIdx.x;
        __nv_bfloat16* w2 = reinterpret_cast<__nv_bfloat16*>(g_w4);
        float e = 0.f, kv = 0.f;
        if (tid < 288) {
            kv = k[tid * 64 + co];
            e  = __expf(kv + 5.0f);
            w2[co * 320 + tid] = __float2bfloat16(e - dwp[0]);
        } else {
            w2[co * 320 + tid] = __float2bfloat16(0.f);
        }
        pe[tid] = e; pk[tid] = kv;
        __syncthreads();
        for (int s = 160; s >= 5; s >>= 1) {
            if (tid < s) { pe[tid] += pe[tid + s]; pk[tid] += pk[tid + s]; }
            __syncthreads();
        }
        if (tid == 0) {
            float SE = pe[0] + pe[1] + pe[2] + pe[3] + pe[4];
            float SK = pk[0] + pk[1] + pk[2] + pk[3] + pk[4];
            g_C[co] = SE - dxp[0] * SK + bias[co];
        }
    } else {
        // ---- x -> bf16 [b][hp][wp][ci], zero borders (pad=1) ----
        int p = (blockIdx.x - 64) * 320 + tid;
        if (p < 7200) {
            int b   = p / 900, rem = p - b * 900;
            int hp  = rem / 30, wp = rem - hp * 30;
            if (hp == 0 || hp == 29 || wp == 0 || wp == 29) {
                uint4 z = make_uint4(0, 0, 0, 0);
                g_xt4[p * 4 + 0] = z; g_xt4[p * 4 + 1] = z;
                g_xt4[p * 4 + 2] = z; g_xt4[p * 4 + 3] = z;
            } else {
                const float* xs = x + (size_t)b * 32 * 784 + (hp - 1) * 28 + (wp - 1);
                __nv_bfloat162 buf[16];
                #pragma unroll
                for (int j = 0; j < 16; j++)
                    buf[j] = __floats2bfloat162_rn(xs[(2 * j) * 784], xs[(2 * j + 1) * 784]);
                const uint4* u = reinterpret_cast<const uint4*>(buf);
                g_xt4[p * 4 + 0] = u[0]; g_xt4[p * 4 + 1] = u[1];
                g_xt4[p * 4 + 2] = u[2]; g_xt4[p * 4 + 3] = u[3];
            }
        }
    }
}

// ---------------- Kernel 2: implicit-GEMM conv via HMMA ----------------
// smem: A 64 rows x 592B (stride 37 uint4, conflict-free ldmatrix), B same, C.
constexpr int STRB  = 592;                 // 37 * 16
constexpr int OFF_A = 0;                   // 64*592 = 37888
constexpr int OFF_B = 37888;               // 64*592 = 37888
constexpr int OFF_C = 75776;               // 64 floats
constexpr int SMEMB = OFF_C + 256;
constexpr int CNT   = 512;                 // 16 warps

__global__ void __launch_bounds__(CNT) conv_mma_kernel(float* __restrict__ out)
{
    extern __shared__ __align__(16) char sm[];
    const uint32_t smb = smem_u32(sm);
    uint4* sA4 = reinterpret_cast<uint4*>(sm + OFF_A);
    uint4* sB4 = reinterpret_cast<uint4*>(sm + OFF_B);
    float* sC  = reinterpret_cast<float*>(sm + OFF_C);

    const int tid  = threadIdx.x;
    const int wid  = tid >> 5;
    const int lane = tid & 31;
    const int t    = blockIdx.x;            // M-tile (98 tiles of 64 rows)

    if (tid < 64) sC[tid] = g_C[tid];

    // ---- stage A (im2col rows) and B (W''^T) into smem: 2304 chunks ----
    #pragma unroll
    for (int i = 0; i < 5; i++) {
        int q = i * CNT + tid;
        if (q < 2304) {
            int row = q / 36;
            int c36 = q - row * 36;
            int seg = c36 >> 2, c4 = c36 & 3;
            int kh  = seg / 3,  kw = seg - kh * 3;
            int m   = t * 64 + row;
            int b   = m / 784, rem = m - b * 784;
            int h   = rem / 28, w = rem - h * 28;
            sA4[row * 37 + c36] = g_xt4[((b * 30 + h + kh) * 30 + (w + kw)) * 4 + c4];
            sB4[row * 37 + c36] = g_w4[row * 40 + c36];
        }
    }
    __syncthreads();

    // ---- warp tiling: 16 warps = 4(M) x 4(N); warp tile 16M x 16N ----
    const int wm = (wid & 3) * 16;
    const int wn = (wid >> 2) * 16;

    uint32_t aAddr = smb + OFF_A + (uint32_t)(wm + (lane & 15)) * STRB + (lane >> 4) * 16;
    uint32_t bAddr = smb + OFF_B + (uint32_t)(wn + (lane & 15)) * STRB + (lane >> 4) * 16;

    float acc0[8], acc1[8];
    #pragma unroll
    for (int i = 0; i < 8; i++) { acc0[i] = 0.f; acc1[i] = 0.f; }

    // two independent 9-deep K chains (halves the mma dependency depth)
    #pragma unroll
    for (int ks = 0; ks < 9; ks++) {
        uint32_t a0[4], b0[4], a1[4], b1[4];
        ldmx4(a0, aAddr + ks * 32);
        ldmx4(b0, bAddr + ks * 32);
        ldmx4(a1, aAddr + (ks + 9) * 32);
        ldmx4(b1, bAddr + (ks + 9) * 32);
        mma16816(acc0 + 0, a0, b0[0], b0[2]);
        mma16816(acc0 + 4, a0, b0[1], b0[3]);
        mma16816(acc1 + 0, a1, b1[0], b1[2]);
        mma16816(acc1 + 4, a1, b1[1], b1[3]);
    }
    #pragma unroll
    for (int i = 0; i < 8; i++) acc0[i] += acc1[i];

    // ---- epilogue: D frag -> out[b][co][h][w] + C[co] ----
    {
        const int row  = lane >> 2;
        const int colp = (lane & 3) * 2;
        int m0 = t * 64 + wm + row;
        int m1 = m0 + 8;
        int b0i = m0 / 784, r0 = m0 - b0i * 784;
        int b1i = m1 / 784, r1 = m1 - b1i * 784;
        float* o0 = out + (size_t)b0i * 64 * 784 + r0;
        float* o1 = out + (size_t)b1i * 64 * 784 + r1;
        #pragma unroll
        for (int j = 0; j < 2; j++) {
            int co = wn + j * 8 + colp;
            float c0 = sC[co], c1 = sC[co + 1];
            o0[(size_t)(co    ) * 784] = acc0[j * 4 + 0] + c0;
            o0[(size_t)(co + 1) * 784] = acc0[j * 4 + 1] + c1;
            o1[(size_t)(co    ) * 784] = acc0[j * 4 + 2] + c0;
            o1[(size_t)(co + 1) * 784] = acc0[j * 4 + 3] + c1;
        }
    }
}

// ---------------- launch ----------------
extern "C" void kernel_launch(void* const* d_in, const int* in_sizes, int n_in,
                              void* d_out, int out_size)
{
    (void)in_sizes; (void)n_in; (void)out_size;
    const float* x    = (const float*)d_in[0];
    const float* k    = (const float*)d_in[1];
    const float* bias = (const float*)d_in[2];
    const float* dx   = (const float*)d_in[3];
    const float* dw   = (const float*)d_in[4];
    float* out        = (float*)d_out;

    cudaFuncSetAttribute(conv_mma_kernel,
                         cudaFuncAttributeMaxDynamicSharedMemorySize, SMEMB);

    prep_kernel<<<87, 320>>>(x, k, bias, dx, dw);   // 64 weight + 23 x-transpose blocks
    conv_mma_kernel<<<98, CNT, SMEMB>>>(out);       // one 64-row M-tile per CTA, single wave
}

// round 13
// speedup vs baseline: 3.1347x; 1.0030x over previous
#include <cuda_runtime.h>
#include <cuda_bf16.h>
#include <cstdint>

// Algebraic collapse (alpha=1): exp(lse) = sum_r exp(ln(x_r+1)+k_r+5) = sum_r (x_r+1)e^{k_r+5}
// -> out[m,co] = sum_r A[m,r]*W''[r,co] + C[co]
// GEMM M=6272(=98x64), N=64, K=288(=18 k16 steps) via mma.sync.m16n8k16 bf16.
// R13: cp.async staging (no div on the chunk path), smem-transposed coalesced
// epilogue (kills the 784-strided STG scatter), 2 K-chains.

#define B_   8
#define H_   28
#define W_   28

__device__ uint4 g_xt4[8 * 30 * 30 * 4];   // bf16 [8][30][30][32], padded borders = 0
__device__ uint4 g_w4[64 * 40];            // bf16 [64][320] = W''^T, cols 288..319 = 0
__device__ float g_C[64];

__device__ __forceinline__ uint32_t smem_u32(const void* p) {
    uint32_t a;
    asm("{ .reg .u64 t; cvta.to.shared.u64 t, %1; cvt.u32.u64 %0, t; }" : "=r"(a) : "l"(p));
    return a;
}
__device__ __forceinline__ void cpasync16(uint32_t dst, const void* src) {
    asm volatile("{ .reg .u64 g; cvta.to.global.u64 g, %1; "
                 "cp.async.ca.shared.global [%0], [g], 16; }"
                 :: "r"(dst), "l"(src) : "memory");
}
__device__ __forceinline__ void cpasync_wait() {
    asm volatile("cp.async.commit_group;\n\tcp.async.wait_group 0;" ::: "memory");
}
__device__ __forceinline__ void ldmx4(uint32_t* r, uint32_t addr) {
    asm volatile("ldmatrix.sync.aligned.m8n8.x4.shared.b16 {%0,%1,%2,%3}, [%4];"
                 : "=r"(r[0]), "=r"(r[1]), "=r"(r[2]), "=r"(r[3]) : "r"(addr));
}
__device__ __forceinline__ void mma16816(float* d, const uint32_t* a,
                                         uint32_t b0, uint32_t b1) {
    asm volatile(
        "mma.sync.aligned.m16n8k16.row.col.f32.bf16.bf16.f32 "
        "{%0,%1,%2,%3}, {%4,%5,%6,%7}, {%8,%9}, {%0,%1,%2,%3};"
        : "+f"(d[0]), "+f"(d[1]), "+f"(d[2]), "+f"(d[3])
        : "r"(a[0]), "r"(a[1]), "r"(a[2]), "r"(a[3]), "r"(b0), "r"(b1));
}

// ---------------- Kernel 1: prep (weights + x transpose/pad) ----------------
__global__ void __launch_bounds__(320) prep_kernel(
    const float* __restrict__ x, const float* __restrict__ k,
    const float* __restrict__ bias,
    const float* __restrict__ dxp, const float* __restrict__ dwp)
{
    __shared__ float pe[320], pk[320];
    const int tid = threadIdx.x;

    if (blockIdx.x < 64) {
        const int co = blockIdx.x;
        __nv_bfloat16* w2 = reinterpret_cast<__nv_bfloat16*>(g_w4);
        float e = 0.f, kv = 0.f;
        if (tid < 288) {
            kv = k[tid * 64 + co];
            e  = __expf(kv + 5.0f);
            w2[co * 320 + tid] = __float2bfloat16(e - dwp[0]);
        } else {
            w2[co * 320 + tid] = __float2bfloat16(0.f);
        }
        pe[tid] = e; pk[tid] = kv;
        __syncthreads();
        for (int s = 160; s >= 5; s >>= 1) {
            if (tid < s) { pe[tid] += pe[tid + s]; pk[tid] += pk[tid + s]; }
            __syncthreads();
        }
        if (tid == 0) {
            float SE = pe[0] + pe[1] + pe[2] + pe[3] + pe[4];
            float SK = pk[0] + pk[1] + pk[2] + pk[3] + pk[4];
            g_C[co] = SE - dxp[0] * SK + bias[co];
        }
    } else {
        int p = (blockIdx.x - 64) * 320 + tid;
        if (p < 7200) {
            int b   = p / 900, rem = p - b * 900;
            int hp  = rem / 30, wp = rem - hp * 30;
            if (hp == 0 || hp == 29 || wp == 0 || wp == 29) {
                uint4 z = make_uint4(0, 0, 0, 0);
                g_xt4[p * 4 + 0] = z; g_xt4[p * 4 + 1] = z;
                g_xt4[p * 4 + 2] = z; g_xt4[p * 4 + 3] = z;
            } else {
                const float* xs = x + (size_t)b * 32 * 784 + (hp - 1) * 28 + (wp - 1);
                __nv_bfloat162 buf[16];
                #pragma unroll
                for (int j = 0; j < 16; j++)
                    buf[j] = __floats2bfloat162_rn(xs[(2 * j) * 784], xs[(2 * j + 1) * 784]);
                const uint4* u = reinterpret_cast<const uint4*>(buf);
                g_xt4[p * 4 + 0] = u[0]; g_xt4[p * 4 + 1] = u[1];
                g_xt4[p * 4 + 2] = u[2]; g_xt4[p * 4 + 3] = u[3];
            }
        }
    }
}

// ---------------- Kernel 2: implicit-GEMM conv via HMMA ----------------
constexpr int STRB  = 592;                 // 37 * 16, conflict-free ldmatrix rows
constexpr int OFF_A = 0;                   // 64*592 = 37888 ; sD (64x65 f32) aliases this
constexpr int OFF_B = 37888;               // 64*592 = 37888
constexpr int OFF_C = 75776;               // 64 floats
constexpr int SMEMB = OFF_C + 256;
constexpr int CNT   = 512;                 // 16 warps

__global__ void __launch_bounds__(CNT) conv_mma_kernel(float* __restrict__ out)
{
    extern __shared__ __align__(16) char sm[];
    const uint32_t smb = smem_u32(sm);
    float* sC = reinterpret_cast<float*>(sm + OFF_C);

    const int tid  = threadIdx.x;
    const int wid  = tid >> 5;
    const int lane = tid & 31;
    const int t    = blockIdx.x;            // M-tile (98 tiles of 64 rows)

    if (tid < 64) sC[tid] = g_C[tid];

    // ---- stage A/B via cp.async; thread -> fixed row, so b,h,w computed once ----
    {
        const int row   = tid >> 3;          // 0..63
        const int lane8 = tid & 7;
        int m = t * 64 + row;
        int b = m / 784, rem = m - b * 784;
        int h = rem / 28, w = rem - h * 28;
        const uint4* xbase = &g_xt4[((b * 30 + h) * 30 + w) * 4];
        uint32_t dA = smb + OFF_A + row * STRB;
        uint32_t dB = smb + OFF_B + row * STRB;
        const uint4* wrow = &g_w4[row * 40];
        #pragma unroll
        for (int i = 0; i < 5; i++) {
            int c = lane8 + 8 * i;           // 0..39
            if (c < 36) {
                int seg = c >> 2, c4 = c & 3;
                int kh = seg / 3, kw = seg - kh * 3;   // const after unroll
                cpasync16(dA + c * 16, xbase + (kh * 30 + kw) * 4 + c4);
                cpasync16(dB + c * 16, wrow + c);
            }
        }
    }
    cpasync_wait();
    __syncthreads();

    // ---- warp tiling: 16 warps = 4(M) x 4(N); warp tile 16M x 16N ----
    const int wm = (wid & 3) * 16;
    const int wn = (wid >> 2) * 16;

    uint32_t aAddr = smb + OFF_A + (uint32_t)(wm + (lane & 15)) * STRB + (lane >> 4) * 16;
    uint32_t bAddr = smb + OFF_B + (uint32_t)(wn + (lane & 15)) * STRB + (lane >> 4) * 16;

    float acc0[8], acc1[8];
    #pragma unroll
    for (int i = 0; i < 8; i++) { acc0[i] = 0.f; acc1[i] = 0.f; }

    #pragma unroll
    for (int ks = 0; ks < 9; ks++) {
        uint32_t a0[4], b0[4], a1[4], b1[4];
        ldmx4(a0, aAddr + ks * 32);
        ldmx4(b0, bAddr + ks * 32);
        ldmx4(a1, aAddr + (ks + 9) * 32);
        ldmx4(b1, bAddr + (ks + 9) * 32);
        mma16816(acc0 + 0, a0, b0[0], b0[2]);
        mma16816(acc0 + 4, a0, b0[1], b0[3]);
        mma16816(acc1 + 0, a1, b1[0], b1[2]);
        mma16816(acc1 + 4, a1, b1[1], b1[3]);
    }
    #pragma unroll
    for (int i = 0; i < 8; i++) acc0[i] += acc1[i];

    // ---- epilogue: frags -> smem [co][j] (aliases A), then coalesced STG ----
    __syncthreads();                         // all ldmatrix reads done
    float* sD = reinterpret_cast<float*>(sm + OFF_A);   // stride 65
    {
        const int row  = lane >> 2;
        const int colp = (lane & 3) * 2;
        int j0 = wm + row, j1 = j0 + 8;
        #pragma unroll
        for (int jj = 0; jj < 2; jj++) {
            int co = wn + jj * 8 + colp;
            sD[(co    ) * 65 + j0] = acc0[jj * 4 + 0];
            sD[(co + 1) * 65 + j0] = acc0[jj * 4 + 1];
            sD[(co    ) * 65 + j1] = acc0[jj * 4 + 2];
            sD[(co + 1) * 65 + j1] = acc0[jj * 4 + 3];
        }
    }
    __syncthreads();
    {
        int m0 = t * 64;
        int b0 = m0 / 784;
        int jb = (b0 + 1) * 784 - m0;        // j >= jb -> next batch image
        #pragma unroll
        for (int i = 0; i < 8; i++) {
            int idx = i * CNT + tid;
            int co  = idx >> 6;
            int j   = idx & 63;
            int b   = b0 + (j >= jb ? 1 : 0);
            int hw  = m0 + j - b * 784;
            out[((size_t)(b * 64 + co)) * 784 + hw] = sD[co * 65 + j] + sC[co];
        }
    }
}

// ---------------- launch ----------------
extern "C" void kernel_launch(void* const* d_in, const int* in_sizes, int n_in,
                              void* d_out, int out_size)
{
    (void)in_sizes; (void)n_in; (void)out_size;
    const float* x    = (const float*)d_in[0];
    const float* k    = (const float*)d_in[1];
    const float* bias = (const float*)d_in[2];
    const float* dx   = (const float*)d_in[3];
    const float* dw   = (const float*)d_in[4];
    float* out        = (float*)d_out;

    cudaFuncSetAttribute(conv_mma_kernel,
                         cudaFuncAttributeMaxDynamicSharedMemorySize, SMEMB);

    prep_kernel<<<87, 320>>>(x, k, bias, dx, dw);
    conv_mma_kernel<<<98, CNT, SMEMB>>>(out);
}